// round 6
// baseline (speedup 1.0000x reference)
#include <cuda_runtime.h>
#include <cuda_bf16.h>
#include <stdint.h>
#include <stddef.h>

#define Bsz 64
#define Ssz 128
#define Tsz 64
#define Vsz 10000
#define Esz 128
#define Hsz 256
#define VPAD 10112            // V padded to multiple of 128

// ---------------- device scratch (no dynamic allocation allowed) ----------------
__device__ float g_emb[Bsz * Ssz * Esz];
__device__ float g_xW[Bsz * Ssz * 2048];
__device__ float g_out1[Bsz * Ssz * 2 * Hsz];
__device__ float g_enc[Bsz * Ssz * 2 * Hsz];
__device__ float g_encWa[Bsz * Ssz * Hsz];
__device__ float g_b1c[2048];
__device__ float g_b2c[2048];
__device__ float g_WhhT4[4 * 256 * 1024];
__device__ float g_Wa1T[256 * 256];
__device__ float g_dWT4[640 * 1024];
__device__ float g_h[2][2 * Bsz * Hsz];             // double-buffered h state
__device__ float g_c[2 * Bsz * Hsz];
__device__ float g_hid[Bsz * Hsz];
__device__ float g_xin[Bsz * 640];
__device__ float g_hc[63 * Bsz * 768];

// software barrier state (zero-initialized; self-resetting)
__device__ int g_bcnt[2048];
__device__ int g_bgen[2048];

// bf16 split buffers
__device__ __nv_bfloat16 g_Ahi[8192 * 512];
__device__ __nv_bfloat16 g_Alo[8192 * 512];
__device__ __nv_bfloat16 g_B1hi[2048 * 128], g_B1lo[2048 * 128];
__device__ __nv_bfloat16 g_B2hi[2048 * 512], g_B2lo[2048 * 512];
__device__ __nv_bfloat16 g_BWahi[256 * 512], g_BWalo[256 * 512];
__device__ __nv_bfloat16 g_Bfchi[VPAD * 768], g_Bfclo[VPAD * 768];

// ---------------- fast math helpers ----------------
__device__ __forceinline__ float sigf(float x) {
    return __fdividef(1.f, 1.f + __expf(-x));
}
__device__ __forceinline__ float tanf_(float x) {
    x = fminf(fmaxf(x, -15.f), 15.f);
    float e = __expf(2.f * x);
    return __fdividef(e - 1.f, e + 1.f);
}

// ---------------- inter-block barrier (nb arrivals on group grp) ----------------
__device__ __forceinline__ void group_barrier(int grp, int nb) {
    __syncthreads();
    if (threadIdx.x == 0) {
        volatile int* genp = g_bgen + grp * 32;
        int g0 = *genp;
        __threadfence();
        if (atomicAdd(g_bcnt + grp * 32, 1) == nb - 1) {
            g_bcnt[grp * 32] = 0;
            __threadfence();
            *genp = g0 + 1;
        } else {
            while (*genp == g0) { }
        }
        __threadfence();
    }
    __syncthreads();
}

// ---------------- warp-level bf16 MMA (baseline PTX, works on sm_103) ----------------
__device__ __forceinline__ void mma16816(float* c, const uint32_t* a, const uint32_t* b) {
    asm volatile(
        "mma.sync.aligned.m16n8k16.row.col.f32.bf16.bf16.f32 "
        "{%0,%1,%2,%3}, {%4,%5,%6,%7}, {%8,%9}, {%0,%1,%2,%3};"
        : "+f"(c[0]), "+f"(c[1]), "+f"(c[2]), "+f"(c[3])
        : "r"(a[0]), "r"(a[1]), "r"(a[2]), "r"(a[3]), "r"(b[0]), "r"(b[1]));
}

#define LDSW 72                       // smem row stride (64 data + 8 pad) in bf16
#define TILE_E (128 * LDSW)           // elems per tile buffer
#define TCSM (4 * TILE_E * 2)         // 73728 bytes

// ---------------- bf16 split-precision tensor-core GEMM ----------------
// C[M,N] = (Ahi+Alo)[M,K] @ (Bhi+Blo)[N,K]^T + bias   (3 accumulating terms)
// 128x128 tile, 256 threads (8 warps, 32x64 each), K chunked by 64.
// mode 1: scatter row r -> C[(r&63)*Tsz + (r>>6)+1][*] with row stride Nreal.
__global__ __launch_bounds__(256) void gemm_tc(
    const __nv_bfloat16* __restrict__ Ahi, const __nv_bfloat16* __restrict__ Alo,
    const __nv_bfloat16* __restrict__ Bhi, const __nv_bfloat16* __restrict__ Blo,
    const float* __restrict__ bias, float* __restrict__ C,
    int Mreal, int Nreal, int K, int mode)
{
    extern __shared__ __nv_bfloat16 sm[];
    __nv_bfloat16* sAh = sm;
    __nv_bfloat16* sAl = sm + TILE_E;
    __nv_bfloat16* sBh = sm + 2 * TILE_E;
    __nv_bfloat16* sBl = sm + 3 * TILE_E;

    int tid = threadIdx.x;
    int warp = tid >> 5, lane = tid & 31;
    int m0 = blockIdx.x * 128, n0 = blockIdx.y * 128;
    int mw = (warp >> 1) * 32, nw = (warp & 1) * 64;

    float acc[2][8][4];
#pragma unroll
    for (int i = 0; i < 2; i++)
#pragma unroll
        for (int j = 0; j < 8; j++)
#pragma unroll
            for (int q = 0; q < 4; q++) acc[i][j][q] = 0.f;

    int ar = lane >> 2;                 // fragment row within 8-row group
    int acq = (lane & 3) * 2;           // fragment col pair

    for (int kc = 0; kc < K; kc += 64) {
#pragma unroll
        for (int i = 0; i < 4; i++) {
            int idx = i * 256 + tid;
            int row = idx >> 3, c8 = (idx & 7) * 8;
            size_t ga = (size_t)(m0 + row) * K + kc + c8;
            size_t gb = (size_t)(n0 + row) * K + kc + c8;
            int so = row * LDSW + c8;
            *(uint4*)&sAh[so] = *(const uint4*)&Ahi[ga];
            *(uint4*)&sAl[so] = *(const uint4*)&Alo[ga];
            *(uint4*)&sBh[so] = *(const uint4*)&Bhi[gb];
            *(uint4*)&sBl[so] = *(const uint4*)&Blo[gb];
        }
        __syncthreads();

#pragma unroll
        for (int k16 = 0; k16 < 4; k16++) {
            int kb = k16 * 16 + acq;
            uint32_t afh[2][4], afl[2][4], bf[8][2];
#pragma unroll
            for (int mt = 0; mt < 2; mt++) {
                int base = (mw + mt * 16 + ar) * LDSW + kb;
                afh[mt][0] = *(const uint32_t*)(sAh + base);
                afh[mt][1] = *(const uint32_t*)(sAh + base + 8 * LDSW);
                afh[mt][2] = *(const uint32_t*)(sAh + base + 8);
                afh[mt][3] = *(const uint32_t*)(sAh + base + 8 * LDSW + 8);
                afl[mt][0] = *(const uint32_t*)(sAl + base);
                afl[mt][1] = *(const uint32_t*)(sAl + base + 8 * LDSW);
                afl[mt][2] = *(const uint32_t*)(sAl + base + 8);
                afl[mt][3] = *(const uint32_t*)(sAl + base + 8 * LDSW + 8);
            }
#pragma unroll
            for (int nt = 0; nt < 8; nt++) {
                int base = (nw + nt * 8 + ar) * LDSW + kb;
                bf[nt][0] = *(const uint32_t*)(sBh + base);
                bf[nt][1] = *(const uint32_t*)(sBh + base + 8);
            }
#pragma unroll
            for (int mt = 0; mt < 2; mt++)
#pragma unroll
                for (int nt = 0; nt < 8; nt++) {
                    mma16816(acc[mt][nt], afh[mt], bf[nt]);   // Ahi*Bhi
                }
#pragma unroll
            for (int mt = 0; mt < 2; mt++)
#pragma unroll
                for (int nt = 0; nt < 8; nt++) {
                    mma16816(acc[mt][nt], afl[mt], bf[nt]);   // Alo*Bhi
                }
#pragma unroll
            for (int nt = 0; nt < 8; nt++) {
                int base = (nw + nt * 8 + ar) * LDSW + kb;
                bf[nt][0] = *(const uint32_t*)(sBl + base);
                bf[nt][1] = *(const uint32_t*)(sBl + base + 8);
            }
#pragma unroll
            for (int mt = 0; mt < 2; mt++)
#pragma unroll
                for (int nt = 0; nt < 8; nt++) {
                    mma16816(acc[mt][nt], afh[mt], bf[nt]);   // Ahi*Blo
                }
        }
        __syncthreads();
    }

    // ---- epilogue: bias + store (optional scatter) ----
#pragma unroll
    for (int mt = 0; mt < 2; mt++) {
#pragma unroll
        for (int half = 0; half < 2; half++) {
            int m = m0 + mw + mt * 16 + ar + half * 8;
            if (m >= Mreal) continue;
            float* crow;
            if (mode == 1) {
                int b = m & 63, st = m >> 6;
                crow = C + ((size_t)b * Tsz + st + 1) * (size_t)Nreal;
            } else {
                crow = C + (size_t)m * Nreal;
            }
#pragma unroll
            for (int nt = 0; nt < 8; nt++) {
                int col = n0 + nw + nt * 8 + acq;
                float v0 = acc[mt][nt][half * 2 + 0];
                float v1 = acc[mt][nt][half * 2 + 1];
                if (col < Nreal)     crow[col]     = v0 + (bias ? bias[col] : 0.f);
                if (col + 1 < Nreal) crow[col + 1] = v1 + (bias ? bias[col + 1] : 0.f);
            }
        }
    }
}

// ---------------- fp32 -> bf16 hi/lo split (with row pad + concat offset) ----------------
__global__ void splitbf16(const float* __restrict__ src, __nv_bfloat16* __restrict__ hi,
                          __nv_bfloat16* __restrict__ lo, int rows, int cols, int ld,
                          int coloff, int prows, int rowoff) {
    int i = blockIdx.x * 256 + threadIdx.x;
    if (i >= prows * cols) return;
    int r = i / cols, c = i % cols;
    float x = (r < rows) ? src[(size_t)r * ld + coloff + c] : 0.f;
    __nv_bfloat16 h = __float2bfloat16(x);
    float rem = x - __bfloat162float(h);
    size_t di = (size_t)(r + rowoff) * cols + c;
    hi[di] = h;
    lo[di] = __float2bfloat16(rem);
}

// ---------------- utility kernels ----------------
__global__ void tpose(const float* __restrict__ src, float* __restrict__ dst,
                      int R, int Kc, int ss, int so, int ds, int co) {
    int i = blockIdx.x * 256 + threadIdx.x;
    if (i >= R * Kc) return;
    int r = i % R, k = i / R;
    dst[(size_t)k * ds + co + r] = src[(size_t)r * ss + so + k];
}

__global__ void tpose4(const float* __restrict__ src, float* __restrict__ dst,
                       int R, int Kc) {
    int i = blockIdx.x * 256 + threadIdx.x;
    if (i >= R * Kc) return;
    int r = i % R, k = i / R;
    dst[(size_t)(k >> 2) * (R * 4) + r * 4 + (k & 3)] = src[(size_t)r * Kc + k];
}

__global__ void biascat(const float* __restrict__ f, const float* __restrict__ b,
                        float* __restrict__ dst) {
    int i = blockIdx.x * 256 + threadIdx.x;
    if (i < 1024) { dst[i] = f[i]; dst[1024 + i] = b[i]; }
}

__global__ void embed_gather(const int* __restrict__ src, const float* __restrict__ emb,
                             float* __restrict__ out) {
    int row = blockIdx.x;
    out[(size_t)row * Esz + threadIdx.x] = emb[(size_t)src[row] * Esz + threadIdx.x];
}

// ---------------- persistent encoder LSTM layer (both directions, all steps) ----------------
// grid 128 = (jc:4) + 4*((bg:16) + 16*(dir:2)); group = bid>>2 (4 blocks, shared (d,bg))
__global__ __launch_bounds__(256) void lstm_layer(
    const float* __restrict__ xW, const float* __restrict__ WhhT4,
    float* __restrict__ hbuf, float* __restrict__ cstate,
    float* __restrict__ out)
{
    int bid = blockIdx.x;
    int jc = bid & 3, bg = (bid >> 2) & 15, d = bid >> 6;
    int grp = bid >> 2;                       // 0..31
    int tid = threadIdx.x;
    __shared__ float4 hsm[4][64];
    __shared__ float part[4][4][64];
    float* h0 = hbuf;
    float* h1 = hbuf + 2 * Bsz * Hsz;

    // zero own slice of h (buffer 0) and c
    {
        int bi = tid >> 6, j2 = tid & 63;
        int si = (d * 64 + bg * 4 + bi) * Hsz + jc * 64 + j2;
        h0[si] = 0.f;
        cstate[si] = 0.f;
    }
    group_barrier(grp, 4);

    for (int t = 0; t < Ssz; t++) {
        const float* hprev = (t & 1) ? h1 : h0;
        float* hnext = (t & 1) ? h0 : h1;
        {
            int bi = tid >> 6, k4 = tid & 63;
            hsm[bi][k4] = __ldcg((const float4*)(hprev +
                              (size_t)(d * 64 + bg * 4 + bi) * Hsz) + k4);
        }
        __syncthreads();
        int g = tid >> 6, j = tid & 63;
        const float* Wp = WhhT4 + (size_t)d * (256 * 1024) + (g * 256 + jc * 64 + j) * 4;
        float a0 = 0.f, a1 = 0.f, a2 = 0.f, a3 = 0.f;
#pragma unroll 4
        for (int k4 = 0; k4 < 64; k4++) {
            float4 w = *(const float4*)(Wp + (size_t)k4 * 4096);
            float4 h0v = hsm[0][k4], h1v = hsm[1][k4], h2v = hsm[2][k4], h3v = hsm[3][k4];
            a0 += w.x * h0v.x + w.y * h0v.y + w.z * h0v.z + w.w * h0v.w;
            a1 += w.x * h1v.x + w.y * h1v.y + w.z * h1v.z + w.w * h1v.w;
            a2 += w.x * h2v.x + w.y * h2v.y + w.z * h2v.z + w.w * h2v.w;
            a3 += w.x * h3v.x + w.y * h3v.y + w.z * h3v.z + w.w * h3v.w;
        }
        part[g][0][j] = a0; part[g][1][j] = a1; part[g][2][j] = a2; part[g][3][j] = a3;
        __syncthreads();
        {
            int bi = tid >> 6, j2 = tid & 63;
            int b = bg * 4 + bi, jg = jc * 64 + j2;
            int s = (d == 0) ? t : (Ssz - 1 - t);
            int row = b * Ssz + s;
            const float* xr = xW + (size_t)row * 2048 + d * 1024;
            float gi = part[0][bi][j2] + xr[jg];
            float gf = part[1][bi][j2] + xr[256 + jg];
            float gg = part[2][bi][j2] + xr[512 + jg];
            float go = part[3][bi][j2] + xr[768 + jg];
            int si = (d * 64 + b) * Hsz + jg;
            float c = sigf(gf) * cstate[si] + sigf(gi) * tanf_(gg);
            cstate[si] = c;
            float h = sigf(go) * tanf_(c);
            hnext[si] = h;
            out[(size_t)row * (2 * Hsz) + d * Hsz + jg] = h;
        }
        group_barrier(grp, 4);
    }
}

// ---------------- persistent decoder: all 63 steps in one launch ----------------
// grid 64 x 256. Phase A: block=batch. Phase B: gates, block=(jc8:8, bg8:8).
__global__ __launch_bounds__(256) void decoder_all(
    const int* __restrict__ trg, const int* __restrict__ tfmask,
    const float* __restrict__ enc, const float* __restrict__ encWa,
    const float* __restrict__ Wa1T, const float* __restrict__ ba,
    const float* __restrict__ vvec, const float* __restrict__ dWT4,
    const float* __restrict__ db, const float* __restrict__ demb,
    const float* __restrict__ Wfc, const float* __restrict__ bfc,
    float* __restrict__ xin, float* __restrict__ hid, float* __restrict__ hc)
{
    int bid = blockIdx.x, tid = threadIdx.x;
    __shared__ float hsm_[256], hwa_[256], vs_[256], sc_[128];
    __shared__ float redm_, reds_;
    __shared__ int tok_;
    __shared__ float4 xs4_[8][160];
    __shared__ float part_[4][8][32];
    __shared__ float ax_[768];
    __shared__ float abv_[256];
    __shared__ int abi_[256];

    vs_[tid] = vvec[tid];

    for (int st = 0; st < Tsz - 1; st++) {
        // ============ phase A: block = batch ============
        int b = bid;
        if (st == 0) hsm_[tid] = enc[((size_t)b * Ssz + (Ssz - 1)) * 512 + tid];
        else         hsm_[tid] = __ldcg(&hid[b * 256 + tid]);

        // token select (uniform branch per block)
        if (st == 0) {
            if (tid == 0) tok_ = trg[b * Tsz];
        } else if (tfmask[st] != 0) {
            if (tid == 0) tok_ = trg[b * Tsz + st];
        } else {
            const float* hcp = hc + ((size_t)(st - 1) * Bsz + b) * 768;
            for (int i = tid; i < 768; i += 256) ax_[i] = __ldcg(&hcp[i]);
            __syncthreads();
            float best = -1e30f; int bix = 0;
            for (int v0 = tid; v0 < Vsz; v0 += 256) {
                float s = bfc[v0];
                const float* wr = Wfc + (size_t)v0 * 768;
                for (int k = 0; k < 768; k++) s += ax_[k] * wr[k];
                if (s > best) { best = s; bix = v0; }
            }
            abv_[tid] = best; abi_[tid] = bix;
            __syncthreads();
            for (int off = 128; off; off >>= 1) {
                if (tid < off) {
                    if (abv_[tid + off] > abv_[tid] ||
                        (abv_[tid + off] == abv_[tid] && abi_[tid + off] < abi_[tid])) {
                        abv_[tid] = abv_[tid + off];
                        abi_[tid] = abi_[tid + off];
                    }
                }
                __syncthreads();
            }
            if (tid == 0) tok_ = abi_[0];
        }
        __syncthreads();

        // embed
        if (tid < 128) xin[b * 640 + tid] = demb[(size_t)tok_ * 128 + tid];

        // hWa = hid @ Wa1.T + ba
        {
            float acc = ba[tid];
#pragma unroll 8
            for (int k = 0; k < 256; k++) acc += hsm_[k] * Wa1T[k * 256 + tid];
            hwa_[tid] = acc;
        }
        __syncthreads();

        // attention scores
        {
            int w = tid >> 5, l = tid & 31;
#pragma unroll
            for (int i = 0; i < 16; i++) {
                int s = w * 16 + i;
                const float* ep = encWa + ((size_t)b * Ssz + s) * 256;
                float a2 = 0.f;
#pragma unroll
                for (int q = 0; q < 8; q++) {
                    int h = l + q * 32;
                    a2 += tanf_(hwa_[h] + ep[h]) * vs_[h];
                }
#pragma unroll
                for (int o = 16; o; o >>= 1) a2 += __shfl_xor_sync(0xFFFFFFFFu, a2, o);
                if (l == 0) sc_[s] = a2;
            }
        }
        __syncthreads();
        if (tid < 32) {
            float m = fmaxf(fmaxf(sc_[tid], sc_[tid + 32]), fmaxf(sc_[tid + 64], sc_[tid + 96]));
#pragma unroll
            for (int o = 16; o; o >>= 1) m = fmaxf(m, __shfl_xor_sync(0xFFFFFFFFu, m, o));
            if (tid == 0) redm_ = m;
        }
        __syncthreads();
        float mx = redm_;
        if (tid < Ssz) sc_[tid] = __expf(sc_[tid] - mx);
        __syncthreads();
        if (tid < 32) {
            float s_ = sc_[tid] + sc_[tid + 32] + sc_[tid + 64] + sc_[tid + 96];
#pragma unroll
            for (int o = 16; o; o >>= 1) s_ += __shfl_xor_sync(0xFFFFFFFFu, s_, o);
            if (tid == 0) reds_ = __fdividef(1.f, s_);
        }
        __syncthreads();
        {
            float inv = reds_;
            float c0 = 0.f, c1 = 0.f;
            const float* eb = enc + (size_t)b * Ssz * 512;
            for (int s = 0; s < Ssz; s++) {
                float a = sc_[s] * inv;
                c0 += a * eb[s * 512 + tid];
                c1 += a * eb[s * 512 + 256 + tid];
            }
            xin[b * 640 + 128 + tid] = c0;
            xin[b * 640 + 384 + tid] = c1;
            float* hcb = hc + ((size_t)st * Bsz + b) * 768;
            hcb[256 + tid] = c0;
            hcb[512 + tid] = c1;
        }
        group_barrier(40, 64);

        // ============ phase B: gates, block = (jc8, bg8) ============
        {
            int jc8 = bid & 7, bg8 = bid >> 3;      // 32-j slice, 8 batches
            for (int i = tid; i < 8 * 160; i += 256) {
                int bi = i / 160, k4 = i % 160;
                xs4_[bi][k4] = __ldcg((const float4*)(xin +
                                   (size_t)(bg8 * 8 + bi) * 640) + k4);
            }
            __syncthreads();
            int g = tid >> 6, jj = (tid >> 1) & 31, bh = tid & 1;
            const float* Wp = dWT4 + (g * 256 + jc8 * 32 + jj) * 4;
            float s0 = 0.f, s1 = 0.f, s2 = 0.f, s3 = 0.f;
#pragma unroll 4
            for (int k4 = 0; k4 < 160; k4++) {
                float4 w = *(const float4*)(Wp + (size_t)k4 * 4096);
                float4 x0 = xs4_[bh * 4 + 0][k4], x1 = xs4_[bh * 4 + 1][k4];
                float4 x2 = xs4_[bh * 4 + 2][k4], x3 = xs4_[bh * 4 + 3][k4];
                s0 += w.x * x0.x + w.y * x0.y + w.z * x0.z + w.w * x0.w;
                s1 += w.x * x1.x + w.y * x1.y + w.z * x1.z + w.w * x1.w;
                s2 += w.x * x2.x + w.y * x2.y + w.z * x2.z + w.w * x2.w;
                s3 += w.x * x3.x + w.y * x3.y + w.z * x3.z + w.w * x3.w;
            }
            part_[g][bh * 4 + 0][jj] = s0;
            part_[g][bh * 4 + 1][jj] = s1;
            part_[g][bh * 4 + 2][jj] = s2;
            part_[g][bh * 4 + 3][jj] = s3;
            __syncthreads();
            {
                int b8 = tid >> 5, j = tid & 31;
                int jg = jc8 * 32 + j;
                float gi = part_[0][b8][j] + db[jg];
                float gg = part_[2][b8][j] + db[512 + jg];
                float go = part_[3][b8][j] + db[768 + jg];
                float cc = sigf(gi) * tanf_(gg);
                float hh = sigf(go) * tanf_(cc);
                int bb = bg8 * 8 + b8;
                hid[bb * 256 + jg] = hh;
                hc[((size_t)st * Bsz + bb) * 768 + jg] = hh;
            }
        }
        group_barrier(40, 64);
    }
}

__global__ void zero_t0(float* __restrict__ out) {
    int b = blockIdx.x;
    int v = blockIdx.y * 256 + threadIdx.x;
    if (v < Vsz) out[(size_t)b * Tsz * Vsz + v] = 0.f;
}

// ---------------- host launch ----------------
static float* symaddr(const void* sym) {
    void* p = nullptr;
    cudaGetSymbolAddress(&p, sym);
    return (float*)p;
}
static __nv_bfloat16* symaddrb(const void* sym) {
    void* p = nullptr;
    cudaGetSymbolAddress(&p, sym);
    return (__nv_bfloat16*)p;
}

extern "C" void kernel_launch(void* const* d_in, const int* in_sizes, int n_in,
                              void* d_out, int out_size) {
    const int*   src     = (const int*)d_in[0];
    const int*   trg     = (const int*)d_in[1];
    const int*   tfmask  = (const int*)d_in[2];
    const float* enc_emb = (const float*)d_in[3];
    const float* e1f_Wih = (const float*)d_in[4];
    const float* e1f_Whh = (const float*)d_in[5];
    const float* e1f_b   = (const float*)d_in[6];
    const float* e1b_Wih = (const float*)d_in[7];
    const float* e1b_Whh = (const float*)d_in[8];
    const float* e1b_b   = (const float*)d_in[9];
    const float* e2f_Wih = (const float*)d_in[10];
    const float* e2f_Whh = (const float*)d_in[11];
    const float* e2f_b   = (const float*)d_in[12];
    const float* e2b_Wih = (const float*)d_in[13];
    const float* e2b_Whh = (const float*)d_in[14];
    const float* e2b_b   = (const float*)d_in[15];
    const float* dec_emb = (const float*)d_in[16];
    const float* Wa      = (const float*)d_in[17];
    const float* ba      = (const float*)d_in[18];
    const float* vvec    = (const float*)d_in[19];
    const float* dWih    = (const float*)d_in[20];
    const float* db      = (const float*)d_in[21];
    const float* Wfc     = (const float*)d_in[22];
    const float* bfc     = (const float*)d_in[23];
    float* out = (float*)d_out;

    float* p_emb   = symaddr(g_emb);
    float* p_xW    = symaddr(g_xW);
    float* p_out1  = symaddr(g_out1);
    float* p_enc   = symaddr(g_enc);
    float* p_encWa = symaddr(g_encWa);
    float* p_b1c   = symaddr(g_b1c);
    float* p_b2c   = symaddr(g_b2c);
    float* p_WhhT4 = symaddr(g_WhhT4);
    float* p_Wa1T  = symaddr(g_Wa1T);
    float* p_dWT4  = symaddr(g_dWT4);
    float* p_h     = symaddr(g_h);
    float* p_c     = symaddr(g_c);
    float* p_hid   = symaddr(g_hid);
    float* p_xin   = symaddr(g_xin);
    float* p_hc    = symaddr(g_hc);

    __nv_bfloat16* p_Ahi = symaddrb(g_Ahi);
    __nv_bfloat16* p_Alo = symaddrb(g_Alo);
    __nv_bfloat16* p_B1hi = symaddrb(g_B1hi), * p_B1lo = symaddrb(g_B1lo);
    __nv_bfloat16* p_B2hi = symaddrb(g_B2hi), * p_B2lo = symaddrb(g_B2lo);
    __nv_bfloat16* p_BWahi = symaddrb(g_BWahi), * p_BWalo = symaddrb(g_BWalo);
    __nv_bfloat16* p_Bfchi = symaddrb(g_Bfchi), * p_Bfclo = symaddrb(g_Bfclo);

    cudaFuncSetAttribute(gemm_tc, cudaFuncAttributeMaxDynamicSharedMemorySize, TCSM);

    auto nb = [](int n) { return (n + 255) / 256; };

    // ---- weight prep ----
    tpose<<<nb(256 * 256), 256>>>(Wa, p_Wa1T, 256, 256, 768, 0, 256, 0);
    tpose4<<<nb(1024 * 256), 256>>>(e1f_Whh, p_WhhT4 + 0 * 262144, 1024, 256);
    tpose4<<<nb(1024 * 256), 256>>>(e1b_Whh, p_WhhT4 + 1 * 262144, 1024, 256);
    tpose4<<<nb(1024 * 256), 256>>>(e2f_Whh, p_WhhT4 + 2 * 262144, 1024, 256);
    tpose4<<<nb(1024 * 256), 256>>>(e2b_Whh, p_WhhT4 + 3 * 262144, 1024, 256);
    tpose4<<<nb(1024 * 640), 256>>>(dWih, p_dWT4, 1024, 640);
    biascat<<<4, 256>>>(e1f_b, e1b_b, p_b1c);
    biascat<<<4, 256>>>(e2f_b, e2b_b, p_b2c);
    splitbf16<<<nb(1024 * 128), 256>>>(e1f_Wih, p_B1hi, p_B1lo, 1024, 128, 128, 0, 1024, 0);
    splitbf16<<<nb(1024 * 128), 256>>>(e1b_Wih, p_B1hi, p_B1lo, 1024, 128, 128, 0, 1024, 1024);
    splitbf16<<<nb(1024 * 512), 256>>>(e2f_Wih, p_B2hi, p_B2lo, 1024, 512, 512, 0, 1024, 0);
    splitbf16<<<nb(1024 * 512), 256>>>(e2b_Wih, p_B2hi, p_B2lo, 1024, 512, 512, 0, 1024, 1024);
    splitbf16<<<nb(256 * 512), 256>>>(Wa, p_BWahi, p_BWalo, 256, 512, 768, 256, 256, 0);
    splitbf16<<<nb(VPAD * 768), 256>>>(Wfc, p_Bfchi, p_Bfclo, Vsz, 768, 768, 0, VPAD, 0);

    // ---- encoder ----
    embed_gather<<<Bsz * Ssz, Esz>>>(src, enc_emb, p_emb);
    splitbf16<<<nb(8192 * 128), 256>>>(p_emb, p_Ahi, p_Alo, 8192, 128, 128, 0, 8192, 0);
    gemm_tc<<<dim3(64, 16), 256, TCSM>>>(p_Ahi, p_Alo, p_B1hi, p_B1lo, p_b1c, p_xW,
                                         8192, 2048, 128, 0);
    lstm_layer<<<128, 256>>>(p_xW, p_WhhT4, p_h, p_c, p_out1);
    splitbf16<<<nb(8192 * 512), 256>>>(p_out1, p_Ahi, p_Alo, 8192, 512, 512, 0, 8192, 0);
    gemm_tc<<<dim3(64, 16), 256, TCSM>>>(p_Ahi, p_Alo, p_B2hi, p_B2lo, p_b2c, p_xW,
                                         8192, 2048, 512, 0);
    lstm_layer<<<128, 256>>>(p_xW, p_WhhT4 + 2 * 262144, p_h, p_c, p_enc);

    // ---- attention precompute + decoder (single persistent launch) ----
    splitbf16<<<nb(8192 * 512), 256>>>(p_enc, p_Ahi, p_Alo, 8192, 512, 512, 0, 8192, 0);
    gemm_tc<<<dim3(64, 2), 256, TCSM>>>(p_Ahi, p_Alo, p_BWahi, p_BWalo, nullptr, p_encWa,
                                        8192, 256, 512, 0);
    decoder_all<<<64, 256>>>(trg, tfmask, p_enc, p_encWa, p_Wa1T, ba, vvec,
                             p_dWT4, db, dec_emb, Wfc, bfc, p_xin, p_hid, p_hc);

    // ---- final projection on tensor cores: [h,context] @ Wfc.T + bfc ----
    splitbf16<<<nb(4096 * 768), 256>>>(p_hc, p_Ahi, p_Alo, 4032, 768, 768, 0, 4096, 0);
    gemm_tc<<<dim3(32, 79), 256, TCSM>>>(p_Ahi, p_Alo, p_Bfchi, p_Bfclo, bfc, out,
                                         4032, Vsz, 768, 1);
    zero_t0<<<dim3(Bsz, (Vsz + 255) / 256), 256>>>(out);
}